// round 3
// baseline (speedup 1.0000x reference)
#include <cuda_runtime.h>
#include <math.h>

#define T_TOK 8192
#define H_DIM 1024
#define E_NUM 8
#define F_DIM 2048
#define TM 128
#define TN 128
#define TK 8
#define MAX_ROWS (2*T_TOK + E_NUM*TM)   /* 17408: 2T assignments + per-expert pad */
#define MAX_TILES (MAX_ROWS/TM)         /* 136 */

/* ---- scratch (device globals; no allocation allowed) ---- */
__device__ float g_hbuf[(size_t)MAX_ROWS * F_DIM];  /* ~142 MB intermediate */
__device__ int   g_rowmap[MAX_ROWS];
__device__ float g_rowprob[MAX_ROWS];
__device__ int   g_counts[E_NUM];
__device__ int   g_offs[E_NUM];
__device__ int   g_cursor[E_NUM];
__device__ int   g_tile_expert[MAX_TILES];
__device__ int   g_e01[T_TOK*2];
__device__ float g_p01[T_TOK*2];

/* ---------------- init: zero out, counts, cursors; rowmap=-1 ---------------- */
__global__ void init_kernel(float* __restrict__ out, int out_n) {
    int i = blockIdx.x * blockDim.x + threadIdx.x;
    if (i < out_n) out[i] = 0.f;
    if (i < MAX_ROWS) g_rowmap[i] = -1;
    if (i < E_NUM) { g_counts[i] = 0; g_cursor[i] = 0; }
}

/* ---------------- router: one warp per token, 8 logits, top-2 + softmax ----- */
__global__ void router_kernel(const float* __restrict__ x,
                              const float* __restrict__ rw,
                              const float* __restrict__ rb) {
    int gw   = (blockIdx.x * blockDim.x + threadIdx.x) >> 5;
    int lane = threadIdx.x & 31;
    if (gw >= T_TOK) return;
    const float* xp = x + (size_t)gw * H_DIM;
    float acc[E_NUM];
#pragma unroll
    for (int e = 0; e < E_NUM; e++) acc[e] = 0.f;
    for (int k = lane; k < H_DIM; k += 32) {
        float xv = xp[k];
        const float4* w = (const float4*)(rw + (size_t)k * E_NUM);
        float4 w0 = w[0], w1v = w[1];
        acc[0] += xv * w0.x;  acc[1] += xv * w0.y;
        acc[2] += xv * w0.z;  acc[3] += xv * w0.w;
        acc[4] += xv * w1v.x; acc[5] += xv * w1v.y;
        acc[6] += xv * w1v.z; acc[7] += xv * w1v.w;
    }
#pragma unroll
    for (int off = 16; off; off >>= 1)
#pragma unroll
        for (int e = 0; e < E_NUM; e++)
            acc[e] += __shfl_xor_sync(0xffffffffu, acc[e], off);
    if (lane == 0) {
#pragma unroll
        for (int e = 0; e < E_NUM; e++) acc[e] += rb[e];
        int i0 = 0;
#pragma unroll
        for (int e = 1; e < E_NUM; e++) if (acc[e] > acc[i0]) i0 = e;  /* earliest wins ties, like lax.top_k */
        int i1 = (i0 == 0) ? 1 : 0;
#pragma unroll
        for (int e = 0; e < E_NUM; e++)
            if (e != i0 && acc[e] > acc[i1]) i1 = e;
        float s0 = acc[i0], s1 = acc[i1];
        float ex = expf(s1 - s0);           /* s1 <= s0: stable softmax over the 2 */
        float p0 = 1.f / (1.f + ex);
        float p1 = ex / (1.f + ex);
        g_e01[2*gw]   = i0;  g_e01[2*gw+1] = i1;
        g_p01[2*gw]   = p0;  g_p01[2*gw+1] = p1;
        atomicAdd(&g_counts[i0], 1);
        atomicAdd(&g_counts[i1], 1);
    }
}

/* ------------- tiny serial scan: padded expert offsets + tile->expert map --- */
__global__ void scan_kernel() {
    int off = 0;
    for (int e = 0; e < E_NUM; e++) {
        g_offs[e] = off;
        int nt = (g_counts[e] + TM - 1) / TM;
        for (int i = 0; i < nt; i++) g_tile_expert[off / TM + i] = e;
        off += nt * TM;
    }
    for (int i = off / TM; i < MAX_TILES; i++) g_tile_expert[i] = -1;
}

/* ------------- fill compacted per-expert row lists ------------------------- */
__global__ void fill_kernel() {
    int t = blockIdx.x * blockDim.x + threadIdx.x;
    if (t >= T_TOK) return;
#pragma unroll
    for (int s = 0; s < 2; s++) {
        int e   = g_e01[2*t + s];
        int pos = atomicAdd(&g_cursor[e], 1);
        int r   = g_offs[e] + pos;
        g_rowmap[r]  = t;
        g_rowprob[r] = g_p01[2*t + s];
    }
}

/* ------------- GEMM1: h = relu(gather(X) @ W1_e + b1_e) -------------------- */
__global__ __launch_bounds__(256)
void gemm1_kernel(const float* __restrict__ x,
                  const float* __restrict__ w1,
                  const float* __restrict__ b1) {
    int e = g_tile_expert[blockIdx.y];
    if (e < 0) return;
    const float* B = w1 + (size_t)e * H_DIM * F_DIM;
    int row0 = blockIdx.y * TM;
    int col0 = blockIdx.x * TN;

    __shared__ float As[TK][TM];
    __shared__ float Bs[TK][TN];

    int tid = threadIdx.x;
    int tx = tid & 15, ty = tid >> 4;
    int lm = tid >> 1, lh = (tid & 1) * 4;
    int lk = tid >> 5, ln = (tid & 31) * 4;

    int arow = g_rowmap[row0 + lm];
    bool avalid = (arow >= 0);
    const float* Ap = x + (size_t)(avalid ? arow : 0) * H_DIM + lh;
    const float* Bp = B + (size_t)lk * F_DIM + col0 + ln;

    float acc[8][8];
#pragma unroll
    for (int i = 0; i < 8; i++)
#pragma unroll
        for (int j = 0; j < 8; j++) acc[i][j] = 0.f;

    for (int k0 = 0; k0 < H_DIM; k0 += TK) {
        float4 av = avalid ? *(const float4*)(Ap + k0)
                           : make_float4(0.f, 0.f, 0.f, 0.f);
        float4 bv = *(const float4*)(Bp + (size_t)k0 * F_DIM);
        __syncthreads();
        As[lh+0][lm] = av.x; As[lh+1][lm] = av.y;
        As[lh+2][lm] = av.z; As[lh+3][lm] = av.w;
        *(float4*)&Bs[lk][ln] = bv;
        __syncthreads();
#pragma unroll
        for (int k = 0; k < TK; k++) {
            float a[8], b[8];
            *(float4*)(a)   = *(const float4*)&As[k][ty*8];
            *(float4*)(a+4) = *(const float4*)&As[k][ty*8+4];
            *(float4*)(b)   = *(const float4*)&Bs[k][tx*8];
            *(float4*)(b+4) = *(const float4*)&Bs[k][tx*8+4];
#pragma unroll
            for (int i = 0; i < 8; i++)
#pragma unroll
                for (int j = 0; j < 8; j++) acc[i][j] += a[i] * b[j];
        }
    }
#pragma unroll
    for (int i = 0; i < 8; i++) {
        int r = row0 + ty*8 + i;
        if (g_rowmap[r] < 0) continue;
        float* hp = g_hbuf + (size_t)r * F_DIM + col0 + tx*8;
        const float* bp = b1 + (size_t)e * F_DIM + col0 + tx*8;
#pragma unroll
        for (int j = 0; j < 8; j++) {
            float v = acc[i][j] + bp[j];
            hp[j] = v > 0.f ? v : 0.f;
        }
    }
}

/* ------------- GEMM2: out[t] += p * (h @ W2_e + b2_e) ---------------------- */
__global__ __launch_bounds__(256)
void gemm2_kernel(const float* __restrict__ w2,
                  const float* __restrict__ b2,
                  float* __restrict__ out) {
    int e = g_tile_expert[blockIdx.y];
    if (e < 0) return;
    const float* B = w2 + (size_t)e * F_DIM * H_DIM;
    int row0 = blockIdx.y * TM;
    int col0 = blockIdx.x * TN;

    __shared__ float As[TK][TM];
    __shared__ float Bs[TK][TN];

    int tid = threadIdx.x;
    int tx = tid & 15, ty = tid >> 4;
    int lm = tid >> 1, lh = (tid & 1) * 4;
    int lk = tid >> 5, ln = (tid & 31) * 4;

    const float* Ap = g_hbuf + (size_t)(row0 + lm) * F_DIM + lh;
    const float* Bp = B + (size_t)lk * H_DIM + col0 + ln;

    float acc[8][8];
#pragma unroll
    for (int i = 0; i < 8; i++)
#pragma unroll
        for (int j = 0; j < 8; j++) acc[i][j] = 0.f;

    for (int k0 = 0; k0 < F_DIM; k0 += TK) {
        float4 av = *(const float4*)(Ap + k0);
        float4 bv = *(const float4*)(Bp + (size_t)k0 * H_DIM);
        __syncthreads();
        As[lh+0][lm] = av.x; As[lh+1][lm] = av.y;
        As[lh+2][lm] = av.z; As[lh+3][lm] = av.w;
        *(float4*)&Bs[lk][ln] = bv;
        __syncthreads();
#pragma unroll
        for (int k = 0; k < TK; k++) {
            float a[8], b[8];
            *(float4*)(a)   = *(const float4*)&As[k][ty*8];
            *(float4*)(a+4) = *(const float4*)&As[k][ty*8+4];
            *(float4*)(b)   = *(const float4*)&Bs[k][tx*8];
            *(float4*)(b+4) = *(const float4*)&Bs[k][tx*8+4];
#pragma unroll
            for (int i = 0; i < 8; i++)
#pragma unroll
                for (int j = 0; j < 8; j++) acc[i][j] += a[i] * b[j];
        }
    }
#pragma unroll
    for (int i = 0; i < 8; i++) {
        int r = row0 + ty*8 + i;
        int t = g_rowmap[r];
        if (t < 0) continue;
        float p = g_rowprob[r];
        float* op = out + (size_t)t * H_DIM + col0 + tx*8;
        const float* bp = b2 + (size_t)e * H_DIM + col0 + tx*8;
#pragma unroll
        for (int j = 0; j < 8; j++)
            atomicAdd(&op[j], p * (acc[i][j] + bp[j]));
    }
}

extern "C" void kernel_launch(void* const* d_in, const int* in_sizes, int n_in,
                              void* d_out, int out_size) {
    const float* x  = (const float*)d_in[0];
    const float* rw = (const float*)d_in[1];
    const float* rb = (const float*)d_in[2];
    const float* w1 = (const float*)d_in[3];
    const float* b1 = (const float*)d_in[4];
    const float* w2 = (const float*)d_in[5];
    const float* b2 = (const float*)d_in[6];
    float* out = (float*)d_out;

    init_kernel<<<(out_size + 255) / 256, 256>>>(out, out_size);
    router_kernel<<<(T_TOK * 32 + 255) / 256, 256>>>(x, rw, rb);
    scan_kernel<<<1, 1>>>();
    fill_kernel<<<(T_TOK + 255) / 256, 256>>>();
    gemm1_kernel<<<dim3(F_DIM / TN, MAX_TILES), 256>>>(x, w1, b1);
    gemm2_kernel<<<dim3(H_DIM / TN, MAX_TILES), 256>>>(w2, b2, out);
}

// round 5
// speedup vs baseline: 2.2664x; 2.2664x over previous
#include <cuda_runtime.h>
#include <cuda_bf16.h>
#include <math.h>
#include <stdint.h>

#define T_TOK 8192
#define H_DIM 1024
#define E_NUM 8
#define F_DIM 2048
#define TM 128
#define MAX_ROWS (2*T_TOK + E_NUM*TM)   /* 17408 */
#define MAX_TILES (MAX_ROWS/TM)         /* 136   */

#define PITCH 80            /* bytes per 32-bf16 k-row: 64B data + 16B pad (5 segs, coprime w/ 8) */
#define PART  10240         /* 128 rows * 80B */
#define STG   (4*PART)      /* Ahi | Alo | Bhi | Blo = 40960 */
#define NSTG  4
#define SMEM_SROWS (NSTG*STG)          /* 163840 */
#define SMEM_AOFF  (SMEM_SROWS + 512)
#define SMEM_TOTAL (SMEM_AOFF + 512)   /* 164864 */

/* ================= PTX helpers (family-common: sm_80+ only) ================= */
__device__ __forceinline__ uint32_t smem_u32(const void* p) {
    uint32_t a;
    asm("{ .reg .u64 t; cvta.to.shared.u64 t, %1; cvt.u32.u64 %0, t; }" : "=r"(a) : "l"(p));
    return a;
}
#define CP_ASYNC16(saddr, gptr) \
    asm volatile("cp.async.cg.shared.global [%0], [%1], 16;" :: "r"(saddr), "l"(gptr))
#define CP_COMMIT() asm volatile("cp.async.commit_group;" ::: "memory")
#define CP_WAIT2()  asm volatile("cp.async.wait_group 2;" ::: "memory")

__device__ __forceinline__ void ldsm_x4(uint32_t* r, uint32_t addr) {
    asm volatile("ldmatrix.sync.aligned.m8n8.x4.shared.b16 {%0,%1,%2,%3}, [%4];"
        : "=r"(r[0]), "=r"(r[1]), "=r"(r[2]), "=r"(r[3]) : "r"(addr));
}
__device__ __forceinline__ void mma16816(float* d, const uint32_t* a, const uint32_t* b) {
    asm volatile("mma.sync.aligned.m16n8k16.row.col.f32.bf16.bf16.f32 "
        "{%0,%1,%2,%3}, {%4,%5,%6,%7}, {%8,%9}, {%0,%1,%2,%3};"
        : "+f"(d[0]), "+f"(d[1]), "+f"(d[2]), "+f"(d[3])
        : "r"(a[0]), "r"(a[1]), "r"(a[2]), "r"(a[3]), "r"(b[0]), "r"(b[1]));
}

/* ================= scratch (device globals) ================= */
__device__ __nv_bfloat16 g_xhi[(size_t)T_TOK * H_DIM];
__device__ __nv_bfloat16 g_xlo[(size_t)T_TOK * H_DIM];
__device__ __nv_bfloat16 g_w1hi[(size_t)E_NUM * F_DIM * H_DIM];  /* [e][n=F][k=H] */
__device__ __nv_bfloat16 g_w1lo[(size_t)E_NUM * F_DIM * H_DIM];
__device__ __nv_bfloat16 g_w2hi[(size_t)E_NUM * H_DIM * F_DIM];  /* [e][n=H][k=F] */
__device__ __nv_bfloat16 g_w2lo[(size_t)E_NUM * H_DIM * F_DIM];
__device__ __nv_bfloat16 g_hhi[(size_t)MAX_ROWS * F_DIM];        /* pad rows stay 0 */
__device__ __nv_bfloat16 g_hlo[(size_t)MAX_ROWS * F_DIM];
__device__ int   g_rowmap[MAX_ROWS];
__device__ float g_rowprob[MAX_ROWS];
__device__ int   g_counts[E_NUM];
__device__ int   g_offs[E_NUM];
__device__ int   g_cursor[E_NUM];
__device__ int   g_tile_expert[MAX_TILES];
__device__ int   g_e01[T_TOK*2];
__device__ float g_p01[T_TOK*2];

/* ================= small kernels ================= */
__global__ void init_kernel(float* __restrict__ out, int out_n) {
    int i = blockIdx.x * blockDim.x + threadIdx.x;
    if (i < out_n) out[i] = 0.f;
    if (i < MAX_ROWS) g_rowmap[i] = -1;
    if (i < E_NUM) { g_counts[i] = 0; g_cursor[i] = 0; }
}

__global__ void router_kernel(const float* __restrict__ x,
                              const float* __restrict__ rw,
                              const float* __restrict__ rb) {
    int gw   = (blockIdx.x * blockDim.x + threadIdx.x) >> 5;
    int lane = threadIdx.x & 31;
    if (gw >= T_TOK) return;
    const float* xp = x + (size_t)gw * H_DIM;
    float acc[E_NUM];
#pragma unroll
    for (int e = 0; e < E_NUM; e++) acc[e] = 0.f;
    for (int k = lane; k < H_DIM; k += 32) {
        float xv = xp[k];
        const float4* w = (const float4*)(rw + (size_t)k * E_NUM);
        float4 w0 = w[0], w1v = w[1];
        acc[0] += xv * w0.x;  acc[1] += xv * w0.y;
        acc[2] += xv * w0.z;  acc[3] += xv * w0.w;
        acc[4] += xv * w1v.x; acc[5] += xv * w1v.y;
        acc[6] += xv * w1v.z; acc[7] += xv * w1v.w;
    }
#pragma unroll
    for (int off = 16; off; off >>= 1)
#pragma unroll
        for (int e = 0; e < E_NUM; e++)
            acc[e] += __shfl_xor_sync(0xffffffffu, acc[e], off);
    if (lane == 0) {
#pragma unroll
        for (int e = 0; e < E_NUM; e++) acc[e] += rb[e];
        int i0 = 0;
#pragma unroll
        for (int e = 1; e < E_NUM; e++) if (acc[e] > acc[i0]) i0 = e;
        int i1 = (i0 == 0) ? 1 : 0;
#pragma unroll
        for (int e = 0; e < E_NUM; e++)
            if (e != i0 && acc[e] > acc[i1]) i1 = e;
        float ex = expf(acc[i1] - acc[i0]);
        float p0 = 1.f / (1.f + ex);
        float p1 = ex / (1.f + ex);
        g_e01[2*gw] = i0;  g_e01[2*gw+1] = i1;
        g_p01[2*gw] = p0;  g_p01[2*gw+1] = p1;
        atomicAdd(&g_counts[i0], 1);
        atomicAdd(&g_counts[i1], 1);
    }
}

__global__ void scan_kernel() {
    int off = 0;
    for (int e = 0; e < E_NUM; e++) {
        g_offs[e] = off;
        int nt = (g_counts[e] + TM - 1) / TM;
        for (int i = 0; i < nt; i++) g_tile_expert[off / TM + i] = e;
        off += nt * TM;
    }
    for (int i = off / TM; i < MAX_TILES; i++) g_tile_expert[i] = -1;
}

__global__ void fill_kernel() {
    int t = blockIdx.x * blockDim.x + threadIdx.x;
    if (t >= T_TOK) return;
#pragma unroll
    for (int s = 0; s < 2; s++) {
        int e   = g_e01[2*t + s];
        int pos = atomicAdd(&g_cursor[e], 1);
        int r   = g_offs[e] + pos;
        g_rowmap[r]  = t;
        g_rowprob[r] = g_p01[2*t + s];
    }
}

/* x -> split bf16 (hi, lo) */
__global__ void conv_x_kernel(const float* __restrict__ x) {
    size_t i = (size_t)(blockIdx.x * blockDim.x + threadIdx.x) * 4;
    if (i >= (size_t)T_TOK * H_DIM) return;
    float4 v = *(const float4*)(x + i);
    __nv_bfloat162 h0 = __floats2bfloat162_rn(v.x, v.y);
    __nv_bfloat162 h1 = __floats2bfloat162_rn(v.z, v.w);
    __nv_bfloat162 l0 = __floats2bfloat162_rn(v.x - __low2float(h0), v.y - __high2float(h0));
    __nv_bfloat162 l1 = __floats2bfloat162_rn(v.z - __low2float(h1), v.w - __high2float(h1));
    uint2 uh; uh.x = *(unsigned*)&h0; uh.y = *(unsigned*)&h1;
    uint2 ul; ul.x = *(unsigned*)&l0; ul.y = *(unsigned*)&l1;
    *(uint2*)(g_xhi + i) = uh;
    *(uint2*)(g_xlo + i) = ul;
}

/* weights: [E][K][N] fp32 -> transposed split [E][N][K] bf16 hi/lo */
__device__ __forceinline__ void conv_w_body(const float* __restrict__ w,
                                            __nv_bfloat16* __restrict__ dhi,
                                            __nv_bfloat16* __restrict__ dlo,
                                            int K, int N) {
    __shared__ float t[32][33];
    int e  = blockIdx.z;
    int n0 = blockIdx.x * 32;
    int k0 = blockIdx.y * 32;
    int tx = threadIdx.x & 31, ty = threadIdx.x >> 5;
    const float* src = w + (size_t)e * K * N;
#pragma unroll
    for (int r = 0; r < 4; r++)
        t[ty + r*8][tx] = src[(size_t)(k0 + ty + r*8) * N + n0 + tx];
    __syncthreads();
#pragma unroll
    for (int r = 0; r < 4; r++) {
        int n = n0 + ty + r*8;
        float v = t[tx][ty + r*8];
        __nv_bfloat16 h = __float2bfloat16_rn(v);
        __nv_bfloat16 l = __float2bfloat16_rn(v - __bfloat162float(h));
        size_t o = ((size_t)e * N + n) * K + k0 + tx;
        dhi[o] = h;  dlo[o] = l;
    }
}
__global__ void conv_w1_kernel(const float* __restrict__ w) { conv_w_body(w, g_w1hi, g_w1lo, H_DIM, F_DIM); }
__global__ void conv_w2_kernel(const float* __restrict__ w) { conv_w_body(w, g_w2hi, g_w2lo, F_DIM, H_DIM); }

/* ================= mma.sync grouped GEMM core ================= */

__device__ __forceinline__ void load_stage(
    int c, int s, int nch, int tid,
    const __nv_bfloat16* __restrict__ Ahi, const __nv_bfloat16* __restrict__ Alo,
    const __nv_bfloat16* __restrict__ Bhi, const __nv_bfloat16* __restrict__ Blo,
    const unsigned* __restrict__ aoff, int col0, int K, uint32_t sb)
{
    if (c < nch) {
        uint32_t sbase = sb + (uint32_t)s * STG;
#pragma unroll
        for (int t = 0; t < 2; t++) {               /* A hi/lo: 128 rows x 64B */
            int idx = tid + t * 256;
            int r = idx >> 2, seg = idx & 3;
            unsigned off = aoff[r] + (unsigned)c * 32 + seg * 8;
            uint32_t sa = sbase + (uint32_t)r * PITCH + seg * 16;
            CP_ASYNC16(sa, Ahi + off);
            CP_ASYNC16(sa + PART, Alo + off);
        }
#pragma unroll
        for (int t = 0; t < 2; t++) {               /* B hi/lo: 128 n-rows x 64B */
            int idx = tid + t * 256;
            int r = idx >> 2, seg = idx & 3;
            size_t off = (size_t)(col0 + r) * K + c * 32 + seg * 8;
            uint32_t sa = sbase + 2 * PART + (uint32_t)r * PITCH + seg * 16;
            CP_ASYNC16(sa, Bhi + off);
            CP_ASYNC16(sa + PART, Blo + off);
        }
    }
    CP_COMMIT();
}

__device__ __forceinline__ void compute_stage(
    float acc[2][8][4], uint32_t sbase, int lane, int mbase, int nbase)
{
#pragma unroll
    for (int ks = 0; ks < 2; ks++) {
        uint32_t ah[2][4], al[2][4], bh[16], bl[16];
        uint32_t arow = sbase + (uint32_t)(mbase + (lane & 15)) * PITCH
                        + ks * 32 + (lane >> 4) * 16;
#pragma unroll
        for (int mt = 0; mt < 2; mt++) {
            ldsm_x4(ah[mt], arow + mt * 16 * PITCH);
            ldsm_x4(al[mt], arow + mt * 16 * PITCH + PART);
        }
        uint32_t brow = sbase + 2 * PART
                        + (uint32_t)(nbase + ((lane >> 4) & 1) * 8 + (lane & 7)) * PITCH
                        + ks * 32 + ((lane >> 3) & 1) * 16;
#pragma unroll
        for (int p = 0; p < 4; p++) {
            ldsm_x4(&bh[p * 4], brow + p * 16 * PITCH);
            ldsm_x4(&bl[p * 4], brow + p * 16 * PITCH + PART);
        }
#pragma unroll
        for (int mt = 0; mt < 2; mt++)
#pragma unroll
            for (int nt = 0; nt < 8; nt++)
                mma16816(acc[mt][nt], ah[mt], &bh[(nt >> 1) * 4 + (nt & 1) * 2]);
#pragma unroll
        for (int mt = 0; mt < 2; mt++)
#pragma unroll
            for (int nt = 0; nt < 8; nt++)
                mma16816(acc[mt][nt], al[mt], &bh[(nt >> 1) * 4 + (nt & 1) * 2]);
#pragma unroll
        for (int mt = 0; mt < 2; mt++)
#pragma unroll
            for (int nt = 0; nt < 8; nt++)
                mma16816(acc[mt][nt], ah[mt], &bl[(nt >> 1) * 4 + (nt & 1) * 2]);
    }
}

__device__ __forceinline__ void gemm_mainloop(
    float acc[2][8][4],
    const __nv_bfloat16* __restrict__ Ahi, const __nv_bfloat16* __restrict__ Alo,
    const __nv_bfloat16* __restrict__ Bhi, const __nv_bfloat16* __restrict__ Blo,
    const unsigned* __restrict__ aoff, int col0, int K, int nch,
    uint32_t sb, int tid, int lane, int mbase, int nbase)
{
    load_stage(0, 0, nch, tid, Ahi, Alo, Bhi, Blo, aoff, col0, K, sb);
    load_stage(1, 1, nch, tid, Ahi, Alo, Bhi, Blo, aoff, col0, K, sb);
    load_stage(2, 2, nch, tid, Ahi, Alo, Bhi, Blo, aoff, col0, K, sb);
    for (int c = 0; c < nch; c++) {
        CP_WAIT2();
        __syncthreads();
        load_stage(c + 3, (c + 3) & 3, nch, tid, Ahi, Alo, Bhi, Blo, aoff, col0, K, sb);
        compute_stage(acc, sb + (uint32_t)(c & 3) * STG, lane, mbase, nbase);
    }
    __syncthreads();   /* all warps done reading smem before epilogue reuses it */
}

/* ------------- GEMM1: h = relu(gather(X) @ W1_e^T + b1) -> split bf16 ------ */
__global__ __launch_bounds__(256, 1)
void gemm1_mma(const float* __restrict__ b1) {
    int e = g_tile_expert[blockIdx.y];
    if (e < 0) return;
    extern __shared__ char smem[];
    uint32_t sb = smem_u32(smem);
    int tid = threadIdx.x, wid = tid >> 5, lane = tid & 31;
    int row0 = blockIdx.y * TM, col0 = blockIdx.x * TM;
    int mbase = (wid >> 1) * 32, nbase = (wid & 1) * 64;
    int* srows = (int*)(smem + SMEM_SROWS);
    unsigned* aoff = (unsigned*)(smem + SMEM_AOFF);

    if (tid < TM) {
        int rm = g_rowmap[row0 + tid];
        srows[tid] = rm;
        aoff[tid] = (unsigned)((rm < 0 ? 0 : rm) * H_DIM);
    }
    __syncthreads();

    float acc[2][8][4];
#pragma unroll
    for (int i = 0; i < 2; i++)
#pragma unroll
        for (int j = 0; j < 8; j++)
#pragma unroll
            for (int q = 0; q < 4; q++) acc[i][j][q] = 0.f;

    gemm_mainloop(acc, g_xhi, g_xlo,
                  g_w1hi + (size_t)e * F_DIM * H_DIM, g_w1lo + (size_t)e * F_DIM * H_DIM,
                  aoff, col0, H_DIM, H_DIM / 32, sb, tid, lane, mbase, nbase);

    /* stage acc -> smem fp32 [128][132], then vectorized split-bf16 stores */
    float* sacc = (float*)smem;
    int groupID = lane >> 2, tig = lane & 3;
#pragma unroll
    for (int mt = 0; mt < 2; mt++)
#pragma unroll
        for (int nt = 0; nt < 8; nt++) {
            int r = mbase + mt * 16 + groupID;
            int cc = nbase + nt * 8 + tig * 2;
            sacc[r * 132 + cc]         = acc[mt][nt][0];
            sacc[r * 132 + cc + 1]     = acc[mt][nt][1];
            sacc[(r + 8) * 132 + cc]     = acc[mt][nt][2];
            sacc[(r + 8) * 132 + cc + 1] = acc[mt][nt][3];
        }
    __syncthreads();
    int row = tid >> 1, hc = (tid & 1) * 64;
    if (srows[row] >= 0) {
        const float* bp = b1 + (size_t)e * F_DIM + col0 + hc;
        __nv_bfloat16* dh = g_hhi + (size_t)(row0 + row) * F_DIM + col0 + hc;
        __nv_bfloat16* dl = g_hlo + (size_t)(row0 + row) * F_DIM + col0 + hc;
        const float* sp = sacc + row * 132 + hc;
#pragma unroll
        for (int cb = 0; cb < 2; cb++) {
            unsigned uh[16], ul[16];
#pragma unroll
            for (int j = 0; j < 16; j++) {
                float v0 = sp[cb * 32 + 2 * j]     + bp[cb * 32 + 2 * j];
                float v1 = sp[cb * 32 + 2 * j + 1] + bp[cb * 32 + 2 * j + 1];
                v0 = v0 > 0.f ? v0 : 0.f;
                v1 = v1 > 0.f ? v1 : 0.f;
                __nv_bfloat162 h2 = __floats2bfloat162_rn(v0, v1);
                __nv_bfloat162 l2 = __floats2bfloat162_rn(v0 - __low2float(h2),
                                                          v1 - __high2float(h2));
                uh[j] = *(unsigned*)&h2;
                ul[j] = *(unsigned*)&l2;
            }
#pragma unroll
            for (int q = 0; q < 4; q++) {
                *(uint4*)(dh + cb * 32 + q * 8) = make_uint4(uh[4*q], uh[4*q+1], uh[4*q+2], uh[4*q+3]);
                *(uint4*)(dl + cb * 32 + q * 8) = make_uint4(ul[4*q], ul[4*q+1], ul[4*q+2], ul[4*q+3]);
            }
        }
    }
}

/* ------------- GEMM2: out[t] += p * (h @ W2_e^T + b2) ---------------------- */
__global__ __launch_bounds__(256, 1)
void gemm2_mma(const float* __restrict__ b2, float* __restrict__ out) {
    int e = g_tile_expert[blockIdx.y];
    if (e < 0) return;
    extern __shared__ char smem[];
    uint32_t sb = smem_u32(smem);
    int tid = threadIdx.x, wid = tid >> 5, lane = tid & 31;
    int row0 = blockIdx.y * TM, col0 = blockIdx.x * TM;
    int mbase = (wid >> 1) * 32, nbase = (wid & 1) * 64;
    int* srows = (int*)(smem + SMEM_SROWS);
    unsigned* aoff = (unsigned*)(smem + SMEM_AOFF);

    if (tid < TM) {
        srows[tid] = g_rowmap[row0 + tid];
        aoff[tid] = (unsigned)((row0 + tid) * F_DIM);
    }
    __syncthreads();

    float acc[2][8][4];
#pragma unroll
    for (int i = 0; i < 2; i++)
#pragma unroll
        for (int j = 0; j < 8; j++)
#pragma unroll
            for (int q = 0; q < 4; q++) acc[i][j][q] = 0.f;

    gemm_mainloop(acc, g_hhi, g_hlo,
                  g_w2hi + (size_t)e * H_DIM * F_DIM, g_w2lo + (size_t)e * H_DIM * F_DIM,
                  aoff, col0, F_DIM, F_DIM / 32, sb, tid, lane, mbase, nbase);

    float* sacc = (float*)smem;
    int groupID = lane >> 2, tig = lane & 3;
#pragma unroll
    for (int mt = 0; mt < 2; mt++)
#pragma unroll
        for (int nt = 0; nt < 8; nt++) {
            int r = mbase + mt * 16 + groupID;
            int cc = nbase + nt * 8 + tig * 2;
            sacc[r * 132 + cc]         = acc[mt][nt][0];
            sacc[r * 132 + cc + 1]     = acc[mt][nt][1];
            sacc[(r + 8) * 132 + cc]     = acc[mt][nt][2];
            sacc[(r + 8) * 132 + cc + 1] = acc[mt][nt][3];
        }
    __syncthreads();
    int row = tid >> 1, hc = (tid & 1) * 64;
    int rm = srows[row];
    if (rm >= 0) {
        float p = g_rowprob[row0 + row];
        const float* bp = b2 + (size_t)e * H_DIM + col0 + hc;
        float* op = out + (size_t)rm * H_DIM + col0 + hc;
        const float* sp = sacc + row * 132 + hc;
#pragma unroll
        for (int j = 0; j < 64; j++)
            atomicAdd(&op[j], p * (sp[j] + bp[j]));
    }
}

/* ================= launch ================= */
extern "C" void kernel_launch(void* const* d_in, const int* in_sizes, int n_in,
                              void* d_out, int out_size) {
    const float* x  = (const float*)d_in[0];
    const float* rw = (const float*)d_in[1];
    const float* rb = (const float*)d_in[2];
    const float* w1 = (const float*)d_in[3];
    const float* b1 = (const float*)d_in[4];
    const float* w2 = (const float*)d_in[5];
    const float* b2 = (const float*)d_in[6];
    float* out = (float*)d_out;

    cudaFuncSetAttribute(gemm1_mma, cudaFuncAttributeMaxDynamicSharedMemorySize, SMEM_TOTAL);
    cudaFuncSetAttribute(gemm2_mma, cudaFuncAttributeMaxDynamicSharedMemorySize, SMEM_TOTAL);

    init_kernel<<<(out_size + 255) / 256, 256>>>(out, out_size);
    conv_x_kernel<<<(T_TOK * H_DIM / 4 + 255) / 256, 256>>>(x);
    conv_w1_kernel<<<dim3(F_DIM / 32, H_DIM / 32, E_NUM), 256>>>(w1);
    conv_w2_kernel<<<dim3(H_DIM / 32, F_DIM / 32, E_NUM), 256>>>(w2);
    router_kernel<<<(T_TOK * 32 + 255) / 256, 256>>>(x, rw, rb);
    scan_kernel<<<1, 1>>>();
    fill_kernel<<<(T_TOK + 255) / 256, 256>>>();
    gemm1_mma<<<dim3(F_DIM / TM, MAX_TILES), 256, SMEM_TOTAL>>>(b1);
    gemm2_mma<<<dim3(H_DIM / TM, MAX_TILES), 256, SMEM_TOTAL>>>(b2, out);
}

// round 7
// speedup vs baseline: 2.9337x; 1.2944x over previous
#include <cuda_runtime.h>
#include <cuda_fp16.h>
#include <math.h>
#include <stdint.h>

#define T_TOK 8192
#define H_DIM 1024
#define E_NUM 8
#define F_DIM 2048
#define TM 128
#define MAX_ROWS (2*T_TOK + E_NUM*TM)   /* 17408 */
#define MAX_TILES (MAX_ROWS/TM)         /* 136   */

#define PITCH 80            /* bytes per 32-fp16 k-row: 64B data + 16B pad */
#define PART  10240         /* 128 rows * 80B */
#define STG   (3*PART)      /* A | Bhi | Blo = 30720 */
#define NSTG  4
#define SMEM_SROWS (NSTG*STG)          /* 122880 */
#define SMEM_AOFF  (SMEM_SROWS + 512)
#define SMEM_TOTAL (SMEM_AOFF + 512)   /* 123904 */

/* ================= PTX helpers (family-common: sm_80+ only) ================= */
__device__ __forceinline__ uint32_t smem_u32(const void* p) {
    uint32_t a;
    asm("{ .reg .u64 t; cvta.to.shared.u64 t, %1; cvt.u32.u64 %0, t; }" : "=r"(a) : "l"(p));
    return a;
}
#define CP_ASYNC16(saddr, gptr) \
    asm volatile("cp.async.cg.shared.global [%0], [%1], 16;" :: "r"(saddr), "l"(gptr))
#define CP_COMMIT() asm volatile("cp.async.commit_group;" ::: "memory")
#define CP_WAIT2()  asm volatile("cp.async.wait_group 2;" ::: "memory")

__device__ __forceinline__ void ldsm_x4(uint32_t* r, uint32_t addr) {
    asm volatile("ldmatrix.sync.aligned.m8n8.x4.shared.b16 {%0,%1,%2,%3}, [%4];"
        : "=r"(r[0]), "=r"(r[1]), "=r"(r[2]), "=r"(r[3]) : "r"(addr));
}
__device__ __forceinline__ void mma16816(float* d, const uint32_t* a, const uint32_t* b) {
    asm volatile("mma.sync.aligned.m16n8k16.row.col.f32.f16.f16.f32 "
        "{%0,%1,%2,%3}, {%4,%5,%6,%7}, {%8,%9}, {%0,%1,%2,%3};"
        : "+f"(d[0]), "+f"(d[1]), "+f"(d[2]), "+f"(d[3])
        : "r"(a[0]), "r"(a[1]), "r"(a[2]), "r"(a[3]), "r"(b[0]), "r"(b[1]));
}

/* ================= scratch (device globals) ================= */
__device__ __half g_xh[(size_t)T_TOK * H_DIM];                 /* x, single fp16 */
__device__ __half g_w1hi[(size_t)E_NUM * F_DIM * H_DIM];       /* [e][n=F][k=H] */
__device__ __half g_w1lo[(size_t)E_NUM * F_DIM * H_DIM];
__device__ __half g_w2hi[(size_t)E_NUM * H_DIM * F_DIM];       /* [e][n=H][k=F] */
__device__ __half g_w2lo[(size_t)E_NUM * H_DIM * F_DIM];
__device__ __half g_h[(size_t)MAX_ROWS * F_DIM];               /* h, single fp16; pad rows stay 0 */
__device__ int   g_rowmap[MAX_ROWS];
__device__ float g_rowprob[MAX_ROWS];
__device__ int   g_counts[E_NUM];
__device__ int   g_offs[E_NUM];
__device__ int   g_cursor[E_NUM];
__device__ int   g_tile_expert[MAX_TILES];
__device__ int   g_e01[T_TOK*2];
__device__ float g_p01[T_TOK*2];

/* ========== launch 1: zero out + convert x to fp16 + init bookkeeping ====== */
__global__ void init_conv_x(const float* __restrict__ x,
                            float* __restrict__ out, int out_n) {
    int i = blockIdx.x * blockDim.x + threadIdx.x;   /* 2097152 threads */
    size_t xi = (size_t)i * 4;
    if (xi < (size_t)T_TOK * H_DIM) {
        float4 v = *(const float4*)(x + xi);
        __half2 h0 = __floats2half2_rn(v.x, v.y);
        __half2 h1 = __floats2half2_rn(v.z, v.w);
        uint2 u; u.x = *(unsigned*)&h0; u.y = *(unsigned*)&h1;
        *(uint2*)(g_xh + xi) = u;
    }
    if ((int)xi < out_n)
        *(float4*)(out + xi) = make_float4(0.f, 0.f, 0.f, 0.f);
    if (i < MAX_ROWS) g_rowmap[i] = -1;
    if (i < E_NUM) { g_counts[i] = 0; g_cursor[i] = 0; }
}

/* ========== launch 2: both weight transpose+split conversions ============== */
__device__ __forceinline__ void conv_w_body(const float* __restrict__ w,
                                            __half* __restrict__ dhi,
                                            __half* __restrict__ dlo,
                                            int K, int N, int e) {
    __shared__ float t[32][33];
    int n0 = blockIdx.x * 32;
    int k0 = blockIdx.y * 32;
    if (n0 >= N || k0 >= K) return;
    int tx = threadIdx.x & 31, ty = threadIdx.x >> 5;
    const float* src = w + (size_t)e * K * N;
#pragma unroll
    for (int r = 0; r < 4; r++)
        t[ty + r*8][tx] = src[(size_t)(k0 + ty + r*8) * N + n0 + tx];
    __syncthreads();
#pragma unroll
    for (int r = 0; r < 4; r++) {
        int n = n0 + ty + r*8;
        float v = t[tx][ty + r*8];
        __half h = __float2half_rn(v);
        __half l = __float2half_rn(v - __half2float(h));
        size_t o = ((size_t)e * N + n) * K + k0 + tx;
        dhi[o] = h;  dlo[o] = l;
    }
}
__global__ void conv_w_all(const float* __restrict__ w1, const float* __restrict__ w2) {
    int z = blockIdx.z;
    if (z < E_NUM) conv_w_body(w1, g_w1hi, g_w1lo, H_DIM, F_DIM, z);
    else           conv_w_body(w2, g_w2hi, g_w2lo, F_DIM, H_DIM, z - E_NUM);
}

/* ========== launch 3: router ============================================== */
__global__ void router_kernel(const float* __restrict__ x,
                              const float* __restrict__ rw,
                              const float* __restrict__ rb) {
    int gw   = (blockIdx.x * blockDim.x + threadIdx.x) >> 5;
    int lane = threadIdx.x & 31;
    if (gw >= T_TOK) return;
    const float* xp = x + (size_t)gw * H_DIM;
    float acc[E_NUM];
#pragma unroll
    for (int e = 0; e < E_NUM; e++) acc[e] = 0.f;
    for (int k = lane; k < H_DIM; k += 32) {
        float xv = xp[k];
        const float4* w = (const float4*)(rw + (size_t)k * E_NUM);
        float4 w0 = w[0], w1v = w[1];
        acc[0] += xv * w0.x;  acc[1] += xv * w0.y;
        acc[2] += xv * w0.z;  acc[3] += xv * w0.w;
        acc[4] += xv * w1v.x; acc[5] += xv * w1v.y;
        acc[6] += xv * w1v.z; acc[7] += xv * w1v.w;
    }
#pragma unroll
    for (int off = 16; off; off >>= 1)
#pragma unroll
        for (int e = 0; e < E_NUM; e++)
            acc[e] += __shfl_xor_sync(0xffffffffu, acc[e], off);
    if (lane == 0) {
#pragma unroll
        for (int e = 0; e < E_NUM; e++) acc[e] += rb[e];
        int i0 = 0;
#pragma unroll
        for (int e = 1; e < E_NUM; e++) if (acc[e] > acc[i0]) i0 = e;
        int i1 = (i0 == 0) ? 1 : 0;
#pragma unroll
        for (int e = 0; e < E_NUM; e++)
            if (e != i0 && acc[e] > acc[i1]) i1 = e;
        float ex = expf(acc[i1] - acc[i0]);
        float p0 = 1.f / (1.f + ex);
        float p1 = ex / (1.f + ex);
        g_e01[2*gw] = i0;  g_e01[2*gw+1] = i1;
        g_p01[2*gw] = p0;  g_p01[2*gw+1] = p1;
        atomicAdd(&g_counts[i0], 1);
        atomicAdd(&g_counts[i1], 1);
    }
}

/* ========== launch 4: scan ; launch 5: fill =============================== */
__global__ void scan_kernel() {
    int off = 0;
    for (int e = 0; e < E_NUM; e++) {
        g_offs[e] = off;
        int nt = (g_counts[e] + TM - 1) / TM;
        for (int i = 0; i < nt; i++) g_tile_expert[off / TM + i] = e;
        off += nt * TM;
    }
    for (int i = off / TM; i < MAX_TILES; i++) g_tile_expert[i] = -1;
}

__global__ void fill_kernel() {
    int t = blockIdx.x * blockDim.x + threadIdx.x;
    if (t >= T_TOK) return;
#pragma unroll
    for (int s = 0; s < 2; s++) {
        int e   = g_e01[2*t + s];
        int pos = atomicAdd(&g_cursor[e], 1);
        int r   = g_offs[e] + pos;
        g_rowmap[r]  = t;
        g_rowprob[r] = g_p01[2*t + s];
    }
}

/* ================= mma.sync grouped GEMM core (A single, B hi/lo) ========= */

__device__ __forceinline__ void load_stage(
    int c, int s, int nch, int tid,
    const __half* __restrict__ A,
    const __half* __restrict__ Bhi, const __half* __restrict__ Blo,
    const unsigned* __restrict__ aoff, int col0, int K, uint32_t sb)
{
    if (c < nch) {
        uint32_t sbase = sb + (uint32_t)s * STG;
#pragma unroll
        for (int t = 0; t < 2; t++) {               /* A: 128 rows x 64B */
            int idx = tid + t * 256;
            int r = idx >> 2, seg = idx & 3;
            unsigned off = aoff[r] + (unsigned)c * 32 + seg * 8;
            uint32_t sa = sbase + (uint32_t)r * PITCH + seg * 16;
            CP_ASYNC16(sa, A + off);
        }
#pragma unroll
        for (int t = 0; t < 2; t++) {               /* B hi/lo: 128 n-rows x 64B */
            int idx = tid + t * 256;
            int r = idx >> 2, seg = idx & 3;
            size_t off = (size_t)(col0 + r) * K + c * 32 + seg * 8;
            uint32_t sa = sbase + PART + (uint32_t)r * PITCH + seg * 16;
            CP_ASYNC16(sa, Bhi + off);
            CP_ASYNC16(sa + PART, Blo + off);
        }
    }
    CP_COMMIT();
}

__device__ __forceinline__ void compute_stage(
    float acc[2][8][4], uint32_t sbase, int lane, int mbase, int nbase)
{
#pragma unroll
    for (int ks = 0; ks < 2; ks++) {
        uint32_t a[2][4], bh[16], bl[16];
        uint32_t arow = sbase + (uint32_t)(mbase + (lane & 15)) * PITCH
                        + ks * 32 + (lane >> 4) * 16;
#pragma unroll
        for (int mt = 0; mt < 2; mt++)
            ldsm_x4(a[mt], arow + mt * 16 * PITCH);
        uint32_t brow = sbase + PART
                        + (uint32_t)(nbase + ((lane >> 4) & 1) * 8 + (lane & 7)) * PITCH
                        + ks * 32 + ((lane >> 3) & 1) * 16;
#pragma unroll
        for (int p = 0; p < 4; p++) {
            ldsm_x4(&bh[p * 4], brow + p * 16 * PITCH);
            ldsm_x4(&bl[p * 4], brow + p * 16 * PITCH + PART);
        }
#pragma unroll
        for (int mt = 0; mt < 2; mt++)
#pragma unroll
            for (int nt = 0; nt < 8; nt++)
                mma16816(acc[mt][nt], a[mt], &bh[(nt >> 1) * 4 + (nt & 1) * 2]);
#pragma unroll
        for (int mt = 0; mt < 2; mt++)
#pragma unroll
            for (int nt = 0; nt < 8; nt++)
                mma16816(acc[mt][nt], a[mt], &bl[(nt >> 1) * 4 + (nt & 1) * 2]);
    }
}

__device__ __forceinline__ void gemm_mainloop(
    float acc[2][8][4],
    const __half* __restrict__ A,
    const __half* __restrict__ Bhi, const __half* __restrict__ Blo,
    const unsigned* __restrict__ aoff, int col0, int K, int nch,
    uint32_t sb, int tid, int lane, int mbase, int nbase)
{
    load_stage(0, 0, nch, tid, A, Bhi, Blo, aoff, col0, K, sb);
    load_stage(1, 1, nch, tid, A, Bhi, Blo, aoff, col0, K, sb);
    load_stage(2, 2, nch, tid, A, Bhi, Blo, aoff, col0, K, sb);
    for (int c = 0; c < nch; c++) {
        CP_WAIT2();
        __syncthreads();
        load_stage(c + 3, (c + 3) & 3, nch, tid, A, Bhi, Blo, aoff, col0, K, sb);
        compute_stage(acc, sb + (uint32_t)(c & 3) * STG, lane, mbase, nbase);
    }
    __syncthreads();   /* all warps done reading smem before epilogue reuses it */
}

/* ------------- launch 6 (ncu target): GEMM1 -------------------------------- */
__global__ __launch_bounds__(256, 1)
void gemm1_mma(const float* __restrict__ b1) {
    int e = g_tile_expert[blockIdx.y];
    if (e < 0) return;
    extern __shared__ char smem[];
    uint32_t sb = smem_u32(smem);
    int tid = threadIdx.x, wid = tid >> 5, lane = tid & 31;
    int row0 = blockIdx.y * TM, col0 = blockIdx.x * TM;
    int mbase = (wid >> 1) * 32, nbase = (wid & 1) * 64;
    int* srows = (int*)(smem + SMEM_SROWS);
    unsigned* aoff = (unsigned*)(smem + SMEM_AOFF);

    if (tid < TM) {
        int rm = g_rowmap[row0 + tid];
        srows[tid] = rm;
        aoff[tid] = (unsigned)((rm < 0 ? 0 : rm) * H_DIM);
    }
    __syncthreads();

    float acc[2][8][4];
#pragma unroll
    for (int i = 0; i < 2; i++)
#pragma unroll
        for (int j = 0; j < 8; j++)
#pragma unroll
            for (int q = 0; q < 4; q++) acc[i][j][q] = 0.f;

    gemm_mainloop(acc, g_xh,
                  g_w1hi + (size_t)e * F_DIM * H_DIM, g_w1lo + (size_t)e * F_DIM * H_DIM,
                  aoff, col0, H_DIM, H_DIM / 32, sb, tid, lane, mbase, nbase);

    /* stage acc -> smem fp32 [128][132], then vectorized fp16 stores */
    float* sacc = (float*)smem;
    int groupID = lane >> 2, tig = lane & 3;
#pragma unroll
    for (int mt = 0; mt < 2; mt++)
#pragma unroll
        for (int nt = 0; nt < 8; nt++) {
            int r = mbase + mt * 16 + groupID;
            int cc = nbase + nt * 8 + tig * 2;
            sacc[r * 132 + cc]         = acc[mt][nt][0];
            sacc[r * 132 + cc + 1]     = acc[mt][nt][1];
            sacc[(r + 8) * 132 + cc]     = acc[mt][nt][2];
            sacc[(r + 8) * 132 + cc + 1] = acc[mt][nt][3];
        }
    __syncthreads();
    int row = tid >> 1, hc = (tid & 1) * 64;
    if (srows[row] >= 0) {
        const float* bp = b1 + (size_t)e * F_DIM + col0 + hc;
        __half* dh = g_h + (size_t)(row0 + row) * F_DIM + col0 + hc;
        const float* sp = sacc + row * 132 + hc;
        unsigned u[32];
#pragma unroll
        for (int j = 0; j < 32; j++) {
            float v0 = sp[2*j]   + bp[2*j];
            float v1 = sp[2*j+1] + bp[2*j+1];
            v0 = v0 > 0.f ? v0 : 0.f;
            v1 = v1 > 0.f ? v1 : 0.f;
            __half2 h2 = __floats2half2_rn(v0, v1);
            u[j] = *(unsigned*)&h2;
        }
#pragma unroll
        for (int q = 0; q < 8; q++)
            *(uint4*)(dh + q * 8) = make_uint4(u[4*q], u[4*q+1], u[4*q+2], u[4*q+3]);
    }
}

/* ------------- launch 7: GEMM2 -------------------------------------------- */
__global__ __launch_bounds__(256, 1)
void gemm2_mma(const float* __restrict__ b2, float* __restrict__ out) {
    int e = g_tile_expert[blockIdx.y];
    if (e < 0) return;
    extern __shared__ char smem[];
    uint32_t sb = smem_u32(smem);
    int tid = threadIdx.x, wid = tid >> 5, lane = tid & 31;
    int row0 = blockIdx.y * TM, col0 = blockIdx.x * TM;
    int mbase = (wid >> 1) * 32, nbase = (wid & 1) * 64;
    int* srows = (int*)(smem + SMEM_SROWS);
    unsigned* aoff = (unsigned*)(smem + SMEM_AOFF);

    if (tid < TM) {
        srows[tid] = g_rowmap[row0 + tid];
        aoff[tid] = (unsigned)((row0 + tid) * F_DIM);
    }
    __syncthreads();

    float acc[2][8][4];
#pragma unroll
    for (int i = 0; i < 2; i++)
#pragma unroll
        for (int j = 0; j < 8; j++)
#pragma unroll
            for (int q = 0; q < 4; q++) acc[i][j][q] = 0.f;

    gemm_mainloop(acc, g_h,
                  g_w2hi + (size_t)e * H_DIM * F_DIM, g_w2lo + (size_t)e * H_DIM * F_DIM,
                  aoff, col0, F_DIM, F_DIM / 32, sb, tid, lane, mbase, nbase);

    float* sacc = (float*)smem;
    int groupID = lane >> 2, tig = lane & 3;
#pragma unroll
    for (int mt = 0; mt < 2; mt++)
#pragma unroll
        for (int nt = 0; nt < 8; nt++) {
            int r = mbase + mt * 16 + groupID;
            int cc = nbase + nt * 8 + tig * 2;
            sacc[r * 132 + cc]         = acc[mt][nt][0];
            sacc[r * 132 + cc + 1]     = acc[mt][nt][1];
            sacc[(r + 8) * 132 + cc]     = acc[mt][nt][2];
            sacc[(r + 8) * 132 + cc + 1] = acc[mt][nt][3];
        }
    __syncthreads();
    int row = tid >> 1, hc = (tid & 1) * 64;
    int rm = srows[row];
    if (rm >= 0) {
        float p = g_rowprob[row0 + row];
        const float* bp = b2 + (size_t)e * H_DIM + col0 + hc;
        float* op = out + (size_t)rm * H_DIM + col0 + hc;
        const float* sp = sacc + row * 132 + hc;
#pragma unroll
        for (int j = 0; j < 64; j++)
            atomicAdd(&op[j], p * (sp[j] + bp[j]));
    }
}

/* ================= launch ================= */
extern "C" void kernel_launch(void* const* d_in, const int* in_sizes, int n_in,
                              void* d_out, int out_size) {
    const float* x  = (const float*)d_in[0];
    const float* rw = (const float*)d_in[1];
    const float* rb = (const float*)d_in[2];
    const float* w1 = (const float*)d_in[3];
    const float* b1 = (const float*)d_in[4];
    const float* w2 = (const float*)d_in[5];
    const float* b2 = (const float*)d_in[6];
    float* out = (float*)d_out;

    cudaFuncSetAttribute(gemm1_mma, cudaFuncAttributeMaxDynamicSharedMemorySize, SMEM_TOTAL);
    cudaFuncSetAttribute(gemm2_mma, cudaFuncAttributeMaxDynamicSharedMemorySize, SMEM_TOTAL);

    /* 1 */ init_conv_x<<<(T_TOK * H_DIM / 4 + 255) / 256, 256>>>(x, out, out_size);
    /* 2 */ conv_w_all<<<dim3(64, 64, 2 * E_NUM), 256>>>(w1, w2);
    /* 3 */ router_kernel<<<(T_TOK * 32 + 255) / 256, 256>>>(x, rw, rb);
    /* 4 */ scan_kernel<<<1, 1>>>();
    /* 5 */ fill_kernel<<<(T_TOK + 255) / 256, 256>>>();
    /* 6 */ gemm1_mma<<<dim3(F_DIM / TM, MAX_TILES), 256, SMEM_TOTAL>>>(b1);   /* ncu -s 5 lands here */
    /* 7 */ gemm2_mma<<<dim3(H_DIM / TM, MAX_TILES), 256, SMEM_TOTAL>>>(b2, out);
}

// round 8
// speedup vs baseline: 5.2734x; 1.7976x over previous
#include <cuda_runtime.h>
#include <cuda_fp16.h>
#include <math.h>
#include <stdint.h>

#define T_TOK 8192
#define H_DIM 1024
#define E_NUM 8
#define F_DIM 2048
#define TM 128
#define MAX_ROWS (2*T_TOK + E_NUM*TM)   /* 17408 */
#define MAX_TILES (MAX_ROWS/TM)         /* 136   */

#define PITCH 80            /* bytes per 32-fp16 k-row: 64B data + 16B pad */
#define PART  10240         /* 128 rows * 80B */
#define STG   (2*PART)      /* A | B = 20480 */
#define NSTG  4
#define SMEM_SROWS (NSTG*STG)          /* 81920 */
#define SMEM_AOFF  (SMEM_SROWS + 512)
#define SMEM_TOTAL (SMEM_AOFF + 512)   /* 82944 -> 2 CTAs/SM */

/* ================= PTX helpers (family-common: sm_80+ only) ================= */
__device__ __forceinline__ uint32_t smem_u32(const void* p) {
    uint32_t a;
    asm("{ .reg .u64 t; cvta.to.shared.u64 t, %1; cvt.u32.u64 %0, t; }" : "=r"(a) : "l"(p));
    return a;
}
#define CP_ASYNC16(saddr, gptr) \
    asm volatile("cp.async.cg.shared.global [%0], [%1], 16;" :: "r"(saddr), "l"(gptr))
#define CP_COMMIT() asm volatile("cp.async.commit_group;" ::: "memory")
#define CP_WAIT2()  asm volatile("cp.async.wait_group 2;" ::: "memory")

__device__ __forceinline__ void ldsm_x4(uint32_t* r, uint32_t addr) {
    asm volatile("ldmatrix.sync.aligned.m8n8.x4.shared.b16 {%0,%1,%2,%3}, [%4];"
        : "=r"(r[0]), "=r"(r[1]), "=r"(r[2]), "=r"(r[3]) : "r"(addr));
}
__device__ __forceinline__ void mma16816(float* d, const uint32_t* a, const uint32_t* b) {
    asm volatile("mma.sync.aligned.m16n8k16.row.col.f32.f16.f16.f32 "
        "{%0,%1,%2,%3}, {%4,%5,%6,%7}, {%8,%9}, {%0,%1,%2,%3};"
        : "+f"(d[0]), "+f"(d[1]), "+f"(d[2]), "+f"(d[3])
        : "r"(a[0]), "r"(a[1]), "r"(a[2]), "r"(a[3]), "r"(b[0]), "r"(b[1]));
}

/* ================= scratch (device globals) ================= */
__device__ __half g_xh[(size_t)T_TOK * H_DIM];                 /* x, fp16 */
__device__ __half g_w1[(size_t)E_NUM * F_DIM * H_DIM];         /* [e][n=F][k=H] fp16 */
__device__ __half g_w2[(size_t)E_NUM * H_DIM * F_DIM];         /* [e][n=H][k=F] fp16 */
__device__ __half g_h[(size_t)MAX_ROWS * F_DIM];               /* h fp16; pad rows stay 0 */
__device__ int   g_rowmap[MAX_ROWS];
__device__ float g_rowprob[MAX_ROWS];
__device__ int   g_counts[E_NUM];
__device__ int   g_offs[E_NUM];
__device__ int   g_cursor[E_NUM];
__device__ int   g_tile_expert[MAX_TILES];
__device__ int   g_e01[T_TOK*2];
__device__ float g_p01[T_TOK*2];

/* ========== launch 1: zero out + convert x to fp16 + init bookkeeping ====== */
__global__ void init_conv_x(const float* __restrict__ x,
                            float* __restrict__ out, int out_n) {
    int i = blockIdx.x * blockDim.x + threadIdx.x;
    size_t xi = (size_t)i * 4;
    if (xi < (size_t)T_TOK * H_DIM) {
        float4 v = *(const float4*)(x + xi);
        __half2 h0 = __floats2half2_rn(v.x, v.y);
        __half2 h1 = __floats2half2_rn(v.z, v.w);
        uint2 u; u.x = *(unsigned*)&h0; u.y = *(unsigned*)&h1;
        *(uint2*)(g_xh + xi) = u;
    }
    if ((int)xi < out_n)
        *(float4*)(out + xi) = make_float4(0.f, 0.f, 0.f, 0.f);
    if (i < MAX_ROWS) g_rowmap[i] = -1;
    if (i < E_NUM) { g_counts[i] = 0; g_cursor[i] = 0; }
}

/* ========== launch 2: both weight transpose conversions ==================== */
__device__ __forceinline__ void conv_w_body(const float* __restrict__ w,
                                            __half* __restrict__ dst,
                                            int K, int N, int e) {
    __shared__ float t[32][33];
    int n0 = blockIdx.x * 32;
    int k0 = blockIdx.y * 32;
    if (n0 >= N || k0 >= K) return;
    int tx = threadIdx.x & 31, ty = threadIdx.x >> 5;
    const float* src = w + (size_t)e * K * N;
#pragma unroll
    for (int r = 0; r < 4; r++)
        t[ty + r*8][tx] = src[(size_t)(k0 + ty + r*8) * N + n0 + tx];
    __syncthreads();
#pragma unroll
    for (int r = 0; r < 4; r++) {
        int n = n0 + ty + r*8;
        float v = t[tx][ty + r*8];
        dst[((size_t)e * N + n) * K + k0 + tx] = __float2half_rn(v);
    }
}
__global__ void conv_w_all(const float* __restrict__ w1, const float* __restrict__ w2) {
    int z = blockIdx.z;
    if (z < E_NUM) conv_w_body(w1, g_w1, H_DIM, F_DIM, z);
    else           conv_w_body(w2, g_w2, F_DIM, H_DIM, z - E_NUM);
}

/* ========== launch 3: router ============================================== */
__global__ void router_kernel(const float* __restrict__ x,
                              const float* __restrict__ rw,
                              const float* __restrict__ rb) {
    int gw   = (blockIdx.x * blockDim.x + threadIdx.x) >> 5;
    int lane = threadIdx.x & 31;
    if (gw >= T_TOK) return;
    const float* xp = x + (size_t)gw * H_DIM;
    float acc[E_NUM];
#pragma unroll
    for (int e = 0; e < E_NUM; e++) acc[e] = 0.f;
    for (int k = lane; k < H_DIM; k += 32) {
        float xv = xp[k];
        const float4* w = (const float4*)(rw + (size_t)k * E_NUM);
        float4 w0 = w[0], w1v = w[1];
        acc[0] += xv * w0.x;  acc[1] += xv * w0.y;
        acc[2] += xv * w0.z;  acc[3] += xv * w0.w;
        acc[4] += xv * w1v.x; acc[5] += xv * w1v.y;
        acc[6] += xv * w1v.z; acc[7] += xv * w1v.w;
    }
#pragma unroll
    for (int off = 16; off; off >>= 1)
#pragma unroll
        for (int e = 0; e < E_NUM; e++)
            acc[e] += __shfl_xor_sync(0xffffffffu, acc[e], off);
    if (lane == 0) {
#pragma unroll
        for (int e = 0; e < E_NUM; e++) acc[e] += rb[e];
        int i0 = 0;
#pragma unroll
        for (int e = 1; e < E_NUM; e++) if (acc[e] > acc[i0]) i0 = e;
        int i1 = (i0 == 0) ? 1 : 0;
#pragma unroll
        for (int e = 0; e < E_NUM; e++)
            if (e != i0 && acc[e] > acc[i1]) i1 = e;
        float ex = expf(acc[i1] - acc[i0]);
        float p0 = 1.f / (1.f + ex);
        float p1 = ex / (1.f + ex);
        g_e01[2*gw] = i0;  g_e01[2*gw+1] = i1;
        g_p01[2*gw] = p0;  g_p01[2*gw+1] = p1;
        atomicAdd(&g_counts[i0], 1);
        atomicAdd(&g_counts[i1], 1);
    }
}

/* ========== launch 4: scan ; launch 5: fill =============================== */
__global__ void scan_kernel() {
    int off = 0;
    for (int e = 0; e < E_NUM; e++) {
        g_offs[e] = off;
        int nt = (g_counts[e] + TM - 1) / TM;
        for (int i = 0; i < nt; i++) g_tile_expert[off / TM + i] = e;
        off += nt * TM;
    }
    for (int i = off / TM; i < MAX_TILES; i++) g_tile_expert[i] = -1;
}

__global__ void fill_kernel() {
    int t = blockIdx.x * blockDim.x + threadIdx.x;
    if (t >= T_TOK) return;
#pragma unroll
    for (int s = 0; s < 2; s++) {
        int e   = g_e01[2*t + s];
        int pos = atomicAdd(&g_cursor[e], 1);
        int r   = g_offs[e] + pos;
        g_rowmap[r]  = t;
        g_rowprob[r] = g_p01[2*t + s];
    }
}

/* ================= mma.sync grouped GEMM core (all fp16) ================== */

__device__ __forceinline__ void load_stage(
    int c, int s, int nch, int tid,
    const __half* __restrict__ A, const __half* __restrict__ B,
    const unsigned* __restrict__ aoff, int col0, int K, uint32_t sb)
{
    if (c < nch) {
        uint32_t sbase = sb + (uint32_t)s * STG;
#pragma unroll
        for (int t = 0; t < 2; t++) {               /* A: 128 rows x 64B */
            int idx = tid + t * 256;
            int r = idx >> 2, seg = idx & 3;
            unsigned off = aoff[r] + (unsigned)c * 32 + seg * 8;
            uint32_t sa = sbase + (uint32_t)r * PITCH + seg * 16;
            CP_ASYNC16(sa, A + off);
        }
#pragma unroll
        for (int t = 0; t < 2; t++) {               /* B: 128 n-rows x 64B */
            int idx = tid + t * 256;
            int r = idx >> 2, seg = idx & 3;
            size_t off = (size_t)(col0 + r) * K + c * 32 + seg * 8;
            uint32_t sa = sbase + PART + (uint32_t)r * PITCH + seg * 16;
            CP_ASYNC16(sa, B + off);
        }
    }
    CP_COMMIT();
}

__device__ __forceinline__ void compute_stage(
    float acc[2][8][4], uint32_t sbase, int lane, int mbase, int nbase)
{
#pragma unroll
    for (int ks = 0; ks < 2; ks++) {
        uint32_t a[2][4], b[16];
        uint32_t arow = sbase + (uint32_t)(mbase + (lane & 15)) * PITCH
                        + ks * 32 + (lane >> 4) * 16;
#pragma unroll
        for (int mt = 0; mt < 2; mt++)
            ldsm_x4(a[mt], arow + mt * 16 * PITCH);
        uint32_t brow = sbase + PART
                        + (uint32_t)(nbase + ((lane >> 4) & 1) * 8 + (lane & 7)) * PITCH
                        + ks * 32 + ((lane >> 3) & 1) * 16;
#pragma unroll
        for (int p = 0; p < 4; p++)
            ldsm_x4(&b[p * 4], brow + p * 16 * PITCH);
#pragma unroll
        for (int mt = 0; mt < 2; mt++)
#pragma unroll
            for (int nt = 0; nt < 8; nt++)
                mma16816(acc[mt][nt], a[mt], &b[(nt >> 1) * 4 + (nt & 1) * 2]);
    }
}

__device__ __forceinline__ void gemm_mainloop(
    float acc[2][8][4],
    const __half* __restrict__ A, const __half* __restrict__ B,
    const unsigned* __restrict__ aoff, int col0, int K, int nch,
    uint32_t sb, int tid, int lane, int mbase, int nbase)
{
    load_stage(0, 0, nch, tid, A, B, aoff, col0, K, sb);
    load_stage(1, 1, nch, tid, A, B, aoff, col0, K, sb);
    load_stage(2, 2, nch, tid, A, B, aoff, col0, K, sb);
    for (int c = 0; c < nch; c++) {
        CP_WAIT2();
        __syncthreads();
        load_stage(c + 3, (c + 3) & 3, nch, tid, A, B, aoff, col0, K, sb);
        compute_stage(acc, sb + (uint32_t)(c & 3) * STG, lane, mbase, nbase);
    }
    __syncthreads();   /* all warps done reading smem before epilogue reuses it */
}

/* ------------- launch 6 (ncu target): GEMM1 -------------------------------- */
__global__ __launch_bounds__(256, 2)
void gemm1_mma(const float* __restrict__ b1) {
    int e = g_tile_expert[blockIdx.y];
    if (e < 0) return;
    extern __shared__ char smem[];
    uint32_t sb = smem_u32(smem);
    int tid = threadIdx.x, wid = tid >> 5, lane = tid & 31;
    int row0 = blockIdx.y * TM, col0 = blockIdx.x * TM;
    int mbase = (wid >> 1) * 32, nbase = (wid & 1) * 64;
    int* srows = (int*)(smem + SMEM_SROWS);
    unsigned* aoff = (unsigned*)(smem + SMEM_AOFF);

    if (tid < TM) {
        int rm = g_rowmap[row0 + tid];
        srows[tid] = rm;
        aoff[tid] = (unsigned)((rm < 0 ? 0 : rm) * H_DIM);
    }
    __syncthreads();

    float acc[2][8][4];
#pragma unroll
    for (int i = 0; i < 2; i++)
#pragma unroll
        for (int j = 0; j < 8; j++)
#pragma unroll
            for (int q = 0; q < 4; q++) acc[i][j][q] = 0.f;

    gemm_mainloop(acc, g_xh, g_w1 + (size_t)e * F_DIM * H_DIM,
                  aoff, col0, H_DIM, H_DIM / 32, sb, tid, lane, mbase, nbase);

    /* stage acc -> smem fp32 [128][132], then vectorized fp16 stores */
    float* sacc = (float*)smem;
    int groupID = lane >> 2, tig = lane & 3;
#pragma unroll
    for (int mt = 0; mt < 2; mt++)
#pragma unroll
        for (int nt = 0; nt < 8; nt++) {
            int r = mbase + mt * 16 + groupID;
            int cc = nbase + nt * 8 + tig * 2;
            sacc[r * 132 + cc]         = acc[mt][nt][0];
            sacc[r * 132 + cc + 1]     = acc[mt][nt][1];
            sacc[(r + 8) * 132 + cc]     = acc[mt][nt][2];
            sacc[(r + 8) * 132 + cc + 1] = acc[mt][nt][3];
        }
    __syncthreads();
    int row = tid >> 1, hc = (tid & 1) * 64;
    if (srows[row] >= 0) {
        const float* bp = b1 + (size_t)e * F_DIM + col0 + hc;
        __half* dh = g_h + (size_t)(row0 + row) * F_DIM + col0 + hc;
        const float* sp = sacc + row * 132 + hc;
        unsigned u[32];
#pragma unroll
        for (int j = 0; j < 32; j++) {
            float v0 = sp[2*j]   + bp[2*j];
            float v1 = sp[2*j+1] + bp[2*j+1];
            v0 = v0 > 0.f ? v0 : 0.f;
            v1 = v1 > 0.f ? v1 : 0.f;
            __half2 h2 = __floats2half2_rn(v0, v1);
            u[j] = *(unsigned*)&h2;
        }
#pragma unroll
        for (int q = 0; q < 8; q++)
            *(uint4*)(dh + q * 8) = make_uint4(u[4*q], u[4*q+1], u[4*q+2], u[4*q+3]);
    }
}

/* ------------- launch 7: GEMM2 -------------------------------------------- */
__global__ __launch_bounds__(256, 2)
void gemm2_mma(const float* __restrict__ b2, float* __restrict__ out) {
    int e = g_tile_expert[blockIdx.y];
    if (e < 0) return;
    extern __shared__ char smem[];
    uint32_t sb = smem_u32(smem);
    int tid = threadIdx.x, wid = tid >> 5, lane = tid & 31;
    int row0 = blockIdx.y * TM, col0 = blockIdx.x * TM;
    int mbase = (wid >> 1) * 32, nbase = (wid & 1) * 64;
    int* srows = (int*)(smem + SMEM_SROWS);
    unsigned* aoff = (unsigned*)(smem + SMEM_AOFF);

    if (tid < TM) {
        srows[tid] = g_rowmap[row0 + tid];
        aoff[tid] = (unsigned)((row0 + tid) * F_DIM);
    }
    __syncthreads();

    float acc[2][8][4];
#pragma unroll
    for (int i = 0; i < 2; i++)
#pragma unroll
        for (int j = 0; j < 8; j++)
#pragma unroll
            for (int q = 0; q < 4; q++) acc[i][j][q] = 0.f;

    gemm_mainloop(acc, g_h, g_w2 + (size_t)e * H_DIM * F_DIM,
                  aoff, col0, F_DIM, F_DIM / 32, sb, tid, lane, mbase, nbase);

    float* sacc = (float*)smem;
    int groupID = lane >> 2, tig = lane & 3;
#pragma unroll
    for (int mt = 0; mt < 2; mt++)
#pragma unroll
        for (int nt = 0; nt < 8; nt++) {
            int r = mbase + mt * 16 + groupID;
            int cc = nbase + nt * 8 + tig * 2;
            sacc[r * 132 + cc]         = acc[mt][nt][0];
            sacc[r * 132 + cc + 1]     = acc[mt][nt][1];
            sacc[(r + 8) * 132 + cc]     = acc[mt][nt][2];
            sacc[(r + 8) * 132 + cc + 1] = acc[mt][nt][3];
        }
    __syncthreads();
    int row = tid >> 1, hc = (tid & 1) * 64;
    int rm = srows[row];
    if (rm >= 0) {
        float p = g_rowprob[row0 + row];
        const float* bp = b2 + (size_t)e * H_DIM + col0 + hc;
        float* op = out + (size_t)rm * H_DIM + col0 + hc;
        const float* sp = sacc + row * 132 + hc;
#pragma unroll
        for (int j = 0; j < 64; j++)
            atomicAdd(&op[j], p * (sp[j] + bp[j]));
    }
}

/* ================= launch ================= */
extern "C" void kernel_launch(void* const* d_in, const int* in_sizes, int n_in,
                              void* d_out, int out_size) {
    const float* x  = (const float*)d_in[0];
    const float* rw = (const float*)d_in[1];
    const float* rb = (const float*)d_in[2];
    const float* w1 = (const float*)d_in[3];
    const float* b1 = (const float*)d_in[4];
    const float* w2 = (const float*)d_in[5];
    const float* b2 = (const float*)d_in[6];
    float* out = (float*)d_out;

    cudaFuncSetAttribute(gemm1_mma, cudaFuncAttributeMaxDynamicSharedMemorySize, SMEM_TOTAL);
    cudaFuncSetAttribute(gemm2_mma, cudaFuncAttributeMaxDynamicSharedMemorySize, SMEM_TOTAL);

    /* 1 */ init_conv_x<<<(T_TOK * H_DIM / 4 + 255) / 256, 256>>>(x, out, out_size);
    /* 2 */ conv_w_all<<<dim3(64, 64, 2 * E_NUM), 256>>>(w1, w2);
    /* 3 */ router_kernel<<<(T_TOK * 32 + 255) / 256, 256>>>(x, rw, rb);
    /* 4 */ scan_kernel<<<1, 1>>>();
    /* 5 */ fill_kernel<<<(T_TOK + 255) / 256, 256>>>();
    /* 6 */ gemm1_mma<<<dim3(F_DIM / TM, MAX_TILES), 256, SMEM_TOTAL>>>(b1);   /* ncu -s 5 lands here */
    /* 7 */ gemm2_mma<<<dim3(H_DIM / TM, MAX_TILES), 256, SMEM_TOTAL>>>(b2, out);
}